// round 7
// baseline (speedup 1.0000x reference)
#include <cuda_runtime.h>
#include <math.h>
#include <stdint.h>

#define BB  4
#define TT  1024
#define CC  1024
#define NH  16
#define NKVH 4
#define HD  64
#define BT  (BB*TT)
#define FFN 4096
#define CAD 32
#define VECH 12

// ---------------- scratch ----------------------------------------------------
__device__ float g_xn  [BT*CC];
__device__ float g_q   [BT*CC];
__device__ float g_k   [BT*NKVH*HD];
__device__ float g_v   [BT*NKVH*HD];
__device__ float g_y   [BT*CC];
__device__ float g_attn[BT*CC];
__device__ float g_cag [BT*CAD];
__device__ float g_cag2[BT*CAD];
__device__ float g_ca  [BT*CC];
__device__ float g_x1  [BT*CC];
__device__ float g_xm  [BT*CC];
__device__ float g_h   [(size_t)BT*FFN];
__device__ float g_h2  [(size_t)BT*FFN];
__device__ float g_gate[BT*CC];
__device__ float g_mlp [BT*CC];
__device__ float g_vit32[BT*CAD];
__device__ float g_vita[BT];
__device__ float g_vitb[BT];

// ---------------- helpers ----------------------------------------------------
__device__ __forceinline__ float geluf(float x){ return 0.5f*x*(1.0f+erff(x*0.70710678118654752f)); }
__device__ __forceinline__ float sigmf(float x){ return 1.0f/(1.0f+expf(-x)); }

__device__ __forceinline__ void split_tf32(float x, float& hi, float& lo){
    uint32_t h;
    asm("cvt.rna.tf32.f32 %0, %1;" : "=r"(h) : "f"(x));
    hi = __uint_as_float(h);
    float r = x - hi;
    uint32_t l;
    asm("cvt.rna.tf32.f32 %0, %1;" : "=r"(l) : "f"(r));
    lo = __uint_as_float(l);
}

__device__ __forceinline__ void mma_tf32(float* d, const float* a, const float* b){
    asm volatile("mma.sync.aligned.m16n8k8.row.col.f32.tf32.tf32.f32 "
        "{%0,%1,%2,%3}, {%4,%5,%6,%7}, {%8,%9}, {%0,%1,%2,%3};"
        : "+f"(d[0]), "+f"(d[1]), "+f"(d[2]), "+f"(d[3])
        : "r"(__float_as_uint(a[0])), "r"(__float_as_uint(a[1])),
          "r"(__float_as_uint(a[2])), "r"(__float_as_uint(a[3])),
          "r"(__float_as_uint(b[0])), "r"(__float_as_uint(b[1])));
}

__device__ __forceinline__ void cp_async16(float* smem_dst, const float* gsrc, bool pred){
    uint32_t s = (uint32_t)__cvta_generic_to_shared(smem_dst);
    int sz = pred ? 16 : 0;
    asm volatile("cp.async.cg.shared.global [%0], [%1], 16, %2;\n" :: "r"(s), "l"(gsrc), "r"(sz));
}
#define CP_COMMIT() asm volatile("cp.async.commit_group;\n" ::: "memory")
#define CP_WAIT1()  asm volatile("cp.async.wait_group 1;\n" ::: "memory")
#define CP_WAIT0()  asm volatile("cp.async.wait_group 0;\n" ::: "memory")

// ---------------- 3xTF32 pipelined NT GEMM -----------------------------------
// C[M,N] = A[M,K]*B[N,K]^T.  M%128==0, K%32==0, N guarded.
// BM=128 BN=64 BK=32; raw fp32 smem, split in consumer; cp.async double buffer.
#define GST 36
#define TILE_A (128*GST)
#define TILE_B (64*GST)
#define GEMM_SMEM ((2*TILE_A + 2*TILE_B)*4)

template<int EPI>
__global__ void __launch_bounds__(256, 2) gemm_tf32(const float* __restrict__ A,
                                                    const float* __restrict__ Bm,
                                                    float* __restrict__ Cm,
                                                    int M, int N, int K)
{
    extern __shared__ float sm[];
    float* As[2] = { sm, sm + TILE_A };
    float* Bs[2] = { sm + 2*TILE_A, sm + 2*TILE_A + TILE_B };

    const int tid  = threadIdx.x;
    const int bm   = blockIdx.y * 128;
    const int bn   = blockIdx.x * 64;
    const int wid  = tid >> 5, lane = tid & 31;
    const int wm   = wid & 3, wn = wid >> 2;
    const int r    = lane >> 2;
    const int kq   = lane & 3;

    float acc[2][4][4];
    #pragma unroll
    for (int i = 0; i < 2; i++)
        #pragma unroll
        for (int j = 0; j < 4; j++)
            #pragma unroll
            for (int c = 0; c < 4; c++) acc[i][j][c] = 0.f;

    const int KT = K >> 5;

    // issue first tile loads
    {
        #pragma unroll
        for (int it = 0; it < 4; it++) {
            int g = tid + it*256;
            int m = g >> 3, kg = (g & 7) * 4;
            cp_async16(&As[0][m*GST + kg], &A[(size_t)(bm+m)*K + kg], true);
        }
        #pragma unroll
        for (int it = 0; it < 2; it++) {
            int g = tid + it*256;
            int n = g >> 3, kg = (g & 7) * 4;
            cp_async16(&Bs[0][n*GST + kg], &Bm[(size_t)(bn+n)*K + kg], bn + n < N);
        }
        CP_COMMIT();
    }

    for (int kt = 0; kt < KT; kt++) {
        if (kt + 1 < KT) {
            int k0 = (kt+1) << 5;
            int nb = (kt+1) & 1;
            #pragma unroll
            for (int it = 0; it < 4; it++) {
                int g = tid + it*256;
                int m = g >> 3, kg = (g & 7) * 4;
                cp_async16(&As[nb][m*GST + kg], &A[(size_t)(bm+m)*K + k0 + kg], true);
            }
            #pragma unroll
            for (int it = 0; it < 2; it++) {
                int g = tid + it*256;
                int n = g >> 3, kg = (g & 7) * 4;
                cp_async16(&Bs[nb][n*GST + kg], &Bm[(size_t)(bn+n)*K + k0 + kg], bn + n < N);
            }
            CP_COMMIT();
            CP_WAIT1();
        } else {
            CP_WAIT0();
        }
        __syncthreads();

        const float* Ab = As[kt & 1];
        const float* Bb = Bs[kt & 1];
        #pragma unroll
        for (int ch = 0; ch < 4; ch++) {
            const int kb = ch*8 + kq;
            float ah[2][4], al[2][4];
            #pragma unroll
            for (int mt = 0; mt < 2; mt++) {
                int row = wm*32 + mt*16 + r;
                float a0 = Ab[row*GST + kb];
                float a1 = Ab[(row+8)*GST + kb];
                float a2 = Ab[row*GST + kb + 4];
                float a3 = Ab[(row+8)*GST + kb + 4];
                split_tf32(a0, ah[mt][0], al[mt][0]);
                split_tf32(a1, ah[mt][1], al[mt][1]);
                split_tf32(a2, ah[mt][2], al[mt][2]);
                split_tf32(a3, ah[mt][3], al[mt][3]);
            }
            float bh[4][2], bl[4][2];
            #pragma unroll
            for (int nt = 0; nt < 4; nt++) {
                int col = wn*32 + nt*8 + r;
                float b0 = Bb[col*GST + kb];
                float b1 = Bb[col*GST + kb + 4];
                split_tf32(b0, bh[nt][0], bl[nt][0]);
                split_tf32(b1, bh[nt][1], bl[nt][1]);
            }
            #pragma unroll
            for (int mt = 0; mt < 2; mt++)
                #pragma unroll
                for (int nt = 0; nt < 4; nt++) {
                    mma_tf32(acc[mt][nt], ah[mt], bh[nt]);
                    mma_tf32(acc[mt][nt], ah[mt], bl[nt]);
                    mma_tf32(acc[mt][nt], al[mt], bh[nt]);
                }
        }
        __syncthreads();
    }

    #pragma unroll
    for (int mt = 0; mt < 2; mt++) {
        int row0 = bm + wm*32 + mt*16 + r;
        #pragma unroll
        for (int nt = 0; nt < 4; nt++) {
            int col0 = bn + wn*32 + nt*8 + kq*2;
            #pragma unroll
            for (int c = 0; c < 4; c++) {
                int row = row0 + (c >= 2 ? 8 : 0);
                int col = col0 + (c & 1);
                if (col < N) {
                    float v = acc[mt][nt][c];
                    if (EPI == 1) { v = fmaxf(v, 0.f); v = v*v; }
                    else if (EPI == 2) { v = sigmf(v); }
                    else if (EPI == 3) { v = geluf(v); }
                    Cm[(size_t)row*N + col] = v;
                }
            }
        }
    }
}

// ---------------- rmsnorm ----------------------------------------------------
__global__ void rmsnorm_k(const float* __restrict__ in, float* __restrict__ out)
{
    __shared__ float red[256];
    int row = blockIdx.x;
    const float* r = in + (size_t)row*CC;
    float s = 0.f;
    for (int i = threadIdx.x; i < CC; i += 256) { float v = r[i]; s += v*v; }
    red[threadIdx.x] = s; __syncthreads();
    for (int st = 128; st > 0; st >>= 1) {
        if (threadIdx.x < st) red[threadIdx.x] += red[threadIdx.x+st];
        __syncthreads();
    }
    float scale = rsqrtf(red[0]/(float)CC + 1e-6f);
    for (int i = threadIdx.x; i < CC; i += 256) out[(size_t)row*CC + i] = r[i]*scale;
}

// ---------------- ve gate ----------------------------------------------------
__global__ void gatve_k(const float* __restrict__ xn, const float* __restrict__ ve,
                        const float* __restrict__ wg, float* __restrict__ v)
{
    int bt = blockIdx.x;
    int tid = threadIdx.x;
    int kv  = tid >> 6;
    float dot = 0.f;
    #pragma unroll
    for (int c = 0; c < VECH; c++) dot += xn[(size_t)bt*CC + c] * wg[kv*VECH + c];
    float gate = 3.0f * sigmf(dot);
    size_t idx = (size_t)bt*256 + tid;
    v[idx] += gate * ve[idx];
}

// ---------------- rope + per-head rmsnorm * 1.2 ------------------------------
__global__ void ropenorm_k(float* __restrict__ q, const float* __restrict__ cs,
                           const float* __restrict__ sn, int nheads)
{
    int gw   = (blockIdx.x * blockDim.x + threadIdx.x) >> 5;
    int lane = threadIdx.x & 31;
    int total = BT * nheads;
    if (gw >= total) return;
    int bt = gw / nheads, h = gw % nheads;
    int t  = bt % TT;
    float* p = q + ((size_t)bt*nheads + h)*HD;
    float x1 = p[lane], x2 = p[lane+32];
    float c = cs[t*32 + lane], s = sn[t*32 + lane];
    float o1 =  x1*c + x2*s;
    float o2 = -x1*s + x2*c;
    float ss = o1*o1 + o2*o2;
    #pragma unroll
    for (int m = 16; m > 0; m >>= 1) ss += __shfl_xor_sync(0xffffffffu, ss, m);
    float scale = rsqrtf(ss/64.f + 1e-6f) * 1.2f;
    p[lane]    = o1*scale;
    p[lane+32] = o2*scale;
}

// ---------------- tensor-core flash attention with refine conv ---------------
// Br=128, Bc=64. 8 warps, each owns 16 q-rows (softmax = quad shuffles only).
// 3xTF32 for QK^T and PV. smem: Qh Ql | Kh Kl Vth Vtl | Ph Pl (Pv halo unioned
// into Ph/Pl region).
#define FST 68
#define FL_Q  (128*FST)
#define FL_KV (64*FST)
#define FLASH_SMEM ((2*FL_Q + 4*FL_KV + 2*FL_Q)*4)

__global__ void __launch_bounds__(256) flash_mma_k(
    const float* __restrict__ Q, const float* __restrict__ K,
    const float* __restrict__ V, const float* __restrict__ prev,
    const float* __restrict__ rw, const float* __restrict__ alphap,
    float* __restrict__ Y)
{
    extern __shared__ float sm[];
    float* Qh = sm;
    float* Ql = Qh + FL_Q;
    float* Kh = Ql + FL_Q;
    float* Kl = Kh + FL_KV;
    float* Vth = Kl + FL_KV;     // transposed: [d][key]
    float* Vtl = Vth + FL_KV;
    float* Ph = Vtl + FL_KV;     // also Pv halo region (130*FST <= 2*FL_Q)
    float* Pl = Ph + FL_Q;
    float* PU = Ph;              // halo union

    const int tid = threadIdx.x;
    const int wid = tid >> 5, lane = tid & 31;
    const int r   = lane >> 2, kq = lane & 3;
    const int qb  = (int)(gridDim.x - 1 - blockIdx.x);   // heavy blocks first
    const int bh  = blockIdx.y;
    const int b   = bh >> 4, h = bh & 15;
    const int kvh = h >> 2;
    const int q0  = qb * 128;
    const float alpha = alphap[0];
    float w9[9];
    #pragma unroll
    for (int i = 0; i < 9; i++) w9[i] = rw[h*9 + i];

    // load + split Q (128 x 64)
    #pragma unroll
    for (int it = 0; it < 8; it++) {
        int g = tid + it*256;                 // 0..2047 float4s
        int row = g >> 4, c4 = (g & 15) * 4;
        float4 v4 = *(const float4*)&Q[((size_t)(b*TT + q0 + row)*NH + h)*HD + c4];
        float4 h4, l4;
        split_tf32(v4.x, h4.x, l4.x);
        split_tf32(v4.y, h4.y, l4.y);
        split_tf32(v4.z, h4.z, l4.z);
        split_tf32(v4.w, h4.w, l4.w);
        *(float4*)&Qh[row*FST + c4] = h4;
        *(float4*)&Ql[row*FST + c4] = l4;
    }

    const int row0 = wid*16 + r;     // thread's first q row (local)
    float O[8][4];
    #pragma unroll
    for (int nt = 0; nt < 8; nt++)
        #pragma unroll
        for (int c = 0; c < 4; c++) O[nt][c] = 0.f;
    float mrow[2] = {-1e30f, -1e30f};
    float lrow[2] = {0.f, 0.f};

    const float* pbase = prev + (size_t)bh*TT*TT;
    const int kcmax = 2*qb + 1;

    for (int kc = 0; kc <= kcmax; kc++) {
        const int k0 = kc*64;
        // load + split K, V (V transposed)
        #pragma unroll
        for (int it = 0; it < 4; it++) {
            int g = tid + it*256;             // 0..1023 float4s
            int row = g >> 4, c4 = (g & 15) * 4;
            size_t base = ((size_t)(b*TT + k0 + row)*NKVH + kvh)*HD + c4;
            float4 k4 = *(const float4*)&K[base];
            float4 h4, l4;
            split_tf32(k4.x, h4.x, l4.x);
            split_tf32(k4.y, h4.y, l4.y);
            split_tf32(k4.z, h4.z, l4.z);
            split_tf32(k4.w, h4.w, l4.w);
            *(float4*)&Kh[row*FST + c4] = h4;
            *(float4*)&Kl[row*FST + c4] = l4;
            float4 v4 = *(const float4*)&V[base];
            float vh, vl;
            split_tf32(v4.x, vh, vl); Vth[(c4+0)*FST + row] = vh; Vtl[(c4+0)*FST + row] = vl;
            split_tf32(v4.y, vh, vl); Vth[(c4+1)*FST + row] = vh; Vtl[(c4+1)*FST + row] = vl;
            split_tf32(v4.z, vh, vl); Vth[(c4+2)*FST + row] = vh; Vtl[(c4+2)*FST + row] = vl;
            split_tf32(v4.w, vh, vl); Vth[(c4+3)*FST + row] = vh; Vtl[(c4+3)*FST + row] = vl;
        }
        // load prev halo tile: rows q0-1..q0+128 (130), cols k0-1..k0+64 (66)
        for (int i = tid; i < 130*66; i += 256) {
            int rr = i / 66, cc = i - rr*66;
            int gq = q0 - 1 + rr, gk = k0 - 1 + cc;
            float val = 0.f;
            if (gq >= 0 && gq < TT && gk >= 0 && gk < TT)
                val = pbase[(size_t)gq*TT + gk];
            PU[rr*FST + cc] = val;
        }
        __syncthreads();

        // S = Q K^T  (3xTF32)
        float S[8][4];
        #pragma unroll
        for (int nt = 0; nt < 8; nt++)
            #pragma unroll
            for (int c = 0; c < 4; c++) S[nt][c] = 0.f;
        #pragma unroll
        for (int ch = 0; ch < 8; ch++) {
            const int kb = ch*8 + kq;
            float aqh[4] = { Qh[row0*FST+kb], Qh[(row0+8)*FST+kb],
                             Qh[row0*FST+kb+4], Qh[(row0+8)*FST+kb+4] };
            float aql[4] = { Ql[row0*FST+kb], Ql[(row0+8)*FST+kb],
                             Ql[row0*FST+kb+4], Ql[(row0+8)*FST+kb+4] };
            #pragma unroll
            for (int nt = 0; nt < 8; nt++) {
                int col = nt*8 + r;
                float bkh[2] = { Kh[col*FST+kb], Kh[col*FST+kb+4] };
                float bkl[2] = { Kl[col*FST+kb], Kl[col*FST+kb+4] };
                mma_tf32(S[nt], aqh, bkh);
                mma_tf32(S[nt], aqh, bkl);
                mma_tf32(S[nt], aql, bkh);
            }
        }
        // scale + conv refine + causal mask
        #pragma unroll
        for (int nt = 0; nt < 8; nt++) {
            #pragma unroll
            for (int c = 0; c < 4; c++) {
                int lr = row0 + ((c >= 2) ? 8 : 0);
                int lc = nt*8 + kq*2 + (c & 1);
                float cv = 0.f;
                #pragma unroll
                for (int di = 0; di < 3; di++)
                    #pragma unroll
                    for (int dj = 0; dj < 3; dj++)
                        cv += PU[(lr+di)*FST + lc + dj] * w9[di*3+dj];
                float val = S[nt][c]*0.125f + alpha*cv;
                if (k0 + lc > q0 + lr) val = -1e30f;
                S[nt][c] = val;
            }
        }
        // online softmax (quad-local: lanes r*4+kq share rows)
        float corr[2], rsum[2];
        #pragma unroll
        for (int half = 0; half < 2; half++) {
            float rm = -1e30f;
            #pragma unroll
            for (int nt = 0; nt < 8; nt++) {
                rm = fmaxf(rm, S[nt][half*2+0]);
                rm = fmaxf(rm, S[nt][half*2+1]);
            }
            rm = fmaxf(rm, __shfl_xor_sync(0xffffffffu, rm, 1));
            rm = fmaxf(rm, __shfl_xor_sync(0xffffffffu, rm, 2));
            float nm = fmaxf(mrow[half], rm);
            corr[half] = __expf(mrow[half] - nm);
            mrow[half] = nm;
            float ssum = 0.f;
            #pragma unroll
            for (int nt = 0; nt < 8; nt++) {
                float p0 = __expf(S[nt][half*2+0] - nm);
                float p1 = __expf(S[nt][half*2+1] - nm);
                S[nt][half*2+0] = p0; S[nt][half*2+1] = p1;
                ssum += p0 + p1;
            }
            ssum += __shfl_xor_sync(0xffffffffu, ssum, 1);
            ssum += __shfl_xor_sync(0xffffffffu, ssum, 2);
            rsum[half] = ssum;
            lrow[half] = lrow[half]*corr[half] + ssum;
            #pragma unroll
            for (int nt = 0; nt < 8; nt++) {
                O[nt][half*2+0] *= corr[half];
                O[nt][half*2+1] *= corr[half];
            }
        }
        __syncthreads();     // all conv reads of PU done before Ph/Pl overwrite
        // write P (split) to smem
        #pragma unroll
        for (int nt = 0; nt < 8; nt++) {
            #pragma unroll
            for (int c = 0; c < 4; c++) {
                int lr = row0 + ((c >= 2) ? 8 : 0);
                int lc = nt*8 + kq*2 + (c & 1);
                float hi, lo;
                split_tf32(S[nt][c], hi, lo);
                Ph[lr*FST + lc] = hi;
                Pl[lr*FST + lc] = lo;
            }
        }
        __syncthreads();
        // O += P V  (3xTF32); B-frag from transposed V: b = Vt[d][k]
        #pragma unroll
        for (int ch = 0; ch < 8; ch++) {
            const int kb = ch*8 + kq;
            float aph[4] = { Ph[row0*FST+kb], Ph[(row0+8)*FST+kb],
                             Ph[row0*FST+kb+4], Ph[(row0+8)*FST+kb+4] };
            float apl[4] = { Pl[row0*FST+kb], Pl[(row0+8)*FST+kb],
                             Pl[row0*FST+kb+4], Pl[(row0+8)*FST+kb+4] };
            #pragma unroll
            for (int nt = 0; nt < 8; nt++) {
                int d = nt*8 + r;
                float bvh[2] = { Vth[d*FST+kb], Vth[d*FST+kb+4] };
                float bvl[2] = { Vtl[d*FST+kb], Vtl[d*FST+kb+4] };
                mma_tf32(O[nt], aph, bvh);
                mma_tf32(O[nt], aph, bvl);
                mma_tf32(O[nt], apl, bvh);
            }
        }
        __syncthreads();     // before next tile overwrites K/V/PU
    }

    float inv0 = 1.f/lrow[0], inv1 = 1.f/lrow[1];
    #pragma unroll
    for (int nt = 0; nt < 8; nt++) {
        #pragma unroll
        for (int c = 0; c < 4; c++) {
            int rowg = q0 + row0 + ((c >= 2) ? 8 : 0);
            int d = nt*8 + kq*2 + (c & 1);
            Y[((size_t)(b*TT + rowg)*NH + h)*HD + d] = O[nt][c] * ((c >= 2) ? inv1 : inv0);
        }
    }
}

// ---------------- CA channel conv (+gelu) ------------------------------------
__global__ void caconv_gelu_k(const float* __restrict__ g, const float* __restrict__ cw,
                              float* __restrict__ out)
{
    int idx = blockIdx.x*256 + threadIdx.x;
    if (idx >= BT*CAD) return;
    int c = idx & 31;
    int bt = idx >> 5;
    int t = bt & (TT-1);
    float w0 = cw[c*3], w1 = cw[c*3+1], w2 = cw[c*3+2];
    float xm1 = (t > 0)     ? g[idx-CAD] : 0.f;
    float x0  = g[idx];
    float xp1 = (t < TT-1)  ? g[idx+CAD] : 0.f;
    float h = x0 + 0.1f*(w0*xm1 + w1*x0 + w2*xp1);
    out[idx] = geluf(h);
}

// ---------------- fused 4-step FFN depthwise conv ----------------------------
// grid: (FFN/128, TT/32, B). smem ping-pong 40x128 tiles.
__global__ void __launch_bounds__(256) ffnconv4_k(const float* __restrict__ in,
                                                  const float* __restrict__ cw,
                                                  float* __restrict__ out)
{
    __shared__ float sA[40*128];
    __shared__ float sB[40*128];
    const int tid = threadIdx.x;
    const int c0 = blockIdx.x * 128;
    const int t0 = blockIdx.y * 32;
    const int b  = blockIdx.z;
    const int c  = tid & 127;
    const int r0 = tid >> 7;          // 0..1

    for (int i = tid; i < 40*128; i += 256) {
        int rr = i >> 7, cc = i & 127;
        int t = t0 - 4 + rr;
        float val = 0.f;
        if (t >= 0 && t < TT) val = in[((size_t)(b*TT + t))*FFN + c0 + cc];
        sA[i] = val;
    }
    float w0 = cw[(c0+c)*3], w1 = cw[(c0+c)*3+1], w2 = cw[(c0+c)*3+2];
    __syncthreads();

    float* X = sA; float* Y2 = sB;
    #pragma unroll
    for (int it = 0; it < 4; it++) {
        for (int rr = r0; rr < 40; rr += 2) {
            int t = t0 - 4 + rr;
            float x0 = X[rr*128 + c];
            float xm = (rr > 0)  ? X[(rr-1)*128 + c] : 0.f;
            float xp = (rr < 39) ? X[(rr+1)*128 + c] : 0.f;
            float nv = x0 + 0.1f*(w0*xm + w1*x0 + w2*xp);
            if (t < 0 || t >= TT) nv = 0.f;
            Y2[rr*128 + c] = nv;
        }
        __syncthreads();
        float* tmp = X; X = Y2; Y2 = tmp;
    }
    // after 4 iters result is in X; valid rows 4..35
    for (int rr = 4 + r0; rr < 36; rr += 2) {
        int t = t0 - 4 + rr;
        out[((size_t)(b*TT + t))*FFN + c0 + c] = X[rr*128 + c];
    }
}

// ---------------- elementwise ------------------------------------------------
__global__ void x1_k(const float* __restrict__ x, const float* __restrict__ attn,
                     const float* __restrict__ ca, float* __restrict__ x1)
{
    size_t i = (size_t)blockIdx.x*256 + threadIdx.x;
    x1[i] = x[i] + attn[i]*(1.0f + 0.1f*tanhf(ca[i]));
}

__global__ void vitsm_k(const float* __restrict__ vin, float* __restrict__ vout)
{
    int idx = blockIdx.x*256 + threadIdx.x;
    if (idx >= BT) return;
    int b = idx >> 10, t = idx & (TT-1);
    const float* vb = vin + b*TT;
    float s = 0.f;
    #pragma unroll
    for (int o = -2; o <= 2; o++) {
        int tt = t + o;
        if (tt >= 0 && tt < TT) s += vb[tt];
    }
    s *= 0.2f;
    float v = 0.7f*vin[idx] + 0.3f*s;
    vout[idx] = (v > 0.3f) ? v : v*0.1f;
}

__global__ void final_k(const float* __restrict__ x1, const float* __restrict__ mlp,
                        const float* __restrict__ gate, const float* __restrict__ ca,
                        const float* __restrict__ vit, float* __restrict__ out)
{
    size_t i = (size_t)blockIdx.x*256 + threadIdx.x;
    int row = (int)(i >> 10);
    float m = mlp[i]*gate[i]*(1.0f + 0.1f*tanhf(ca[i]));
    out[i] = x1[i] + m*vit[row];
}

// ---------------- host -------------------------------------------------------
static void launch_gemm(const float* A, const float* B, float* C,
                        int M, int N, int K, int epi)
{
    dim3 g((N+63)/64, M/128), b(256);
    switch (epi) {
        case 0: gemm_tf32<0><<<g,b,GEMM_SMEM>>>(A,B,C,M,N,K); break;
        case 1: gemm_tf32<1><<<g,b,GEMM_SMEM>>>(A,B,C,M,N,K); break;
        case 2: gemm_tf32<2><<<g,b,GEMM_SMEM>>>(A,B,C,M,N,K); break;
        default: gemm_tf32<3><<<g,b,GEMM_SMEM>>>(A,B,C,M,N,K); break;
    }
}

extern "C" void kernel_launch(void* const* d_in, const int* in_sizes, int n_in,
                              void* d_out, int out_size)
{
    const float* x       = (const float*)d_in[0];
    const float* ve      = (const float*)d_in[1];
    const float* cosb    = (const float*)d_in[2];
    const float* sinb    = (const float*)d_in[3];
    const float* prev    = (const float*)d_in[4];
    const float* w_q     = (const float*)d_in[5];
    const float* w_k     = (const float*)d_in[6];
    const float* w_v     = (const float*)d_in[7];
    const float* w_o     = (const float*)d_in[8];
    const float* w_veg   = (const float*)d_in[9];
    const float* refw    = (const float*)d_in[10];
    const float* ralpha  = (const float*)d_in[11];
    const float* ca_pi   = (const float*)d_in[12];
    const float* ca_cw   = (const float*)d_in[13];
    const float* ca_po   = (const float*)d_in[14];
    const float* ffn_in  = (const float*)d_in[15];
    const float* ffn_cw  = (const float*)d_in[16];
    const float* ffn_out = (const float*)d_in[17];
    const float* ffn_gate= (const float*)d_in[18];
    const float* vit_w1  = (const float*)d_in[19];
    const float* vit_w2  = (const float*)d_in[20];
    float* out = (float*)d_out;

    static bool attr_done = false;
    if (!attr_done) {
        cudaFuncSetAttribute(gemm_tf32<0>, cudaFuncAttributeMaxDynamicSharedMemorySize, GEMM_SMEM);
        cudaFuncSetAttribute(gemm_tf32<1>, cudaFuncAttributeMaxDynamicSharedMemorySize, GEMM_SMEM);
        cudaFuncSetAttribute(gemm_tf32<2>, cudaFuncAttributeMaxDynamicSharedMemorySize, GEMM_SMEM);
        cudaFuncSetAttribute(gemm_tf32<3>, cudaFuncAttributeMaxDynamicSharedMemorySize, GEMM_SMEM);
        cudaFuncSetAttribute(flash_mma_k, cudaFuncAttributeMaxDynamicSharedMemorySize, FLASH_SMEM);
        attr_done = true;
    }

    float *xn,*q,*k,*v,*y,*attn,*cag,*cag2,*ca,*x1,*xm,*h,*h2,*gate,*mlp,*vit32,*vita,*vitb;
    cudaGetSymbolAddress((void**)&xn,   g_xn);
    cudaGetSymbolAddress((void**)&q,    g_q);
    cudaGetSymbolAddress((void**)&k,    g_k);
    cudaGetSymbolAddress((void**)&v,    g_v);
    cudaGetSymbolAddress((void**)&y,    g_y);
    cudaGetSymbolAddress((void**)&attn, g_attn);
    cudaGetSymbolAddress((void**)&cag,  g_cag);
    cudaGetSymbolAddress((void**)&cag2, g_cag2);
    cudaGetSymbolAddress((void**)&ca,   g_ca);
    cudaGetSymbolAddress((void**)&x1,   g_x1);
    cudaGetSymbolAddress((void**)&xm,   g_xm);
    cudaGetSymbolAddress((void**)&h,    g_h);
    cudaGetSymbolAddress((void**)&h2,   g_h2);
    cudaGetSymbolAddress((void**)&gate, g_gate);
    cudaGetSymbolAddress((void**)&mlp,  g_mlp);
    cudaGetSymbolAddress((void**)&vit32,g_vit32);
    cudaGetSymbolAddress((void**)&vita, g_vita);
    cudaGetSymbolAddress((void**)&vitb, g_vitb);

    rmsnorm_k<<<BT, 256>>>(x, xn);
    launch_gemm(xn, w_q, q, BT, CC, CC, 0);
    launch_gemm(xn, w_k, k, BT, NKVH*HD, CC, 0);
    launch_gemm(xn, w_v, v, BT, NKVH*HD, CC, 0);
    gatve_k<<<BT, 256>>>(xn, ve, w_veg, v);
    ropenorm_k<<<(BT*NH)/8, 256>>>(q, cosb, sinb, NH);
    ropenorm_k<<<(BT*NKVH)/8, 256>>>(k, cosb, sinb, NKVH);
    {
        dim3 g(TT/128, BB*NH);
        flash_mma_k<<<g, 256, FLASH_SMEM>>>(q, k, v, prev, refw, ralpha, y);
    }
    launch_gemm(y, w_o, attn, BT, CC, CC, 0);
    launch_gemm(x, ca_pi, cag, BT, CAD, CC, 0);
    caconv_gelu_k<<<(BT*CAD)/256, 256>>>(cag, ca_cw, cag2);
    launch_gemm(cag2, ca_po, ca, BT, CC, CAD, 0);
    x1_k<<<(BT*CC)/256, 256>>>(x, attn, ca, x1);
    rmsnorm_k<<<BT, 256>>>(x1, xm);
    launch_gemm(xm, ffn_in, h, BT, FFN, CC, 1);
    {
        dim3 g(FFN/128, TT/32, BB);
        ffnconv4_k<<<g, 256>>>(h, ffn_cw, h2);
    }
    launch_gemm(xm, ffn_gate, gate, BT, CC, CC, 2);
    launch_gemm(h2, ffn_out, mlp, BT, CC, FFN, 0);
    launch_gemm(x1, ca_pi, cag, BT, CAD, CC, 0);
    caconv_gelu_k<<<(BT*CAD)/256, 256>>>(cag, ca_cw, cag2);
    launch_gemm(cag2, ca_po, ca, BT, CC, CAD, 0);
    launch_gemm(x1, vit_w1, vit32, BT, CAD, CC, 3);
    launch_gemm(vit32, vit_w2, vita, BT, 1, CAD, 2);
    vitsm_k<<<(BT+255)/256, 256>>>(vita, vitb);
    final_k<<<(BT*CC)/256, 256>>>(x1, mlp, gate, ca, vitb, out);
}